// round 16
// baseline (speedup 1.0000x reference)
#include <cuda_runtime.h>
#include <cuda_fp16.h>
#include <cstdint>

#define N_ROWS 65536
#define D      64
#define NE     1024
#define M_TILE 256                     // rows per CTA (8 warps x TWO m16 tiles)
#define NC     64                      // codes per chunk
#define NUM_CHUNKS (NE / NC)           // 16
#define GRID_MAIN (N_ROWS / M_TILE)    // 256
#define GAP_THRESH 1.5e-4f
#define REFINE_BLOCKS 256
#define REFINE_THREADS 256
#define K3_THREADS 256
#define K3_BLOCKS  (N_ROWS * 8 / K3_THREADS)   // 8 threads/row -> 2048
#define BSTRIDE 72                     // padded smem row stride (elems) = 144 B
#define BUF_BYTES (NC * BSTRIDE * 2)   // 9216 B per buffer
#define INV256  0.00390625f

// ---------------- scratch (no allocations allowed) ----------------
__device__ float g_e2[NE];
__device__ __align__(16) __half g_ef16[NE * D];   // e * 256 in fp16
__device__ int   g_idx[N_ROWS];
__device__ float g_partial[GRID_MAIN];
__device__ int   g_flag_cnt;
__device__ int   g_flag_rows[N_ROWS];

// ---------------- helpers ----------------
__device__ __forceinline__ uint32_t smem_u32(const void* p) {
    uint32_t a;
    asm("{ .reg .u64 t; cvta.to.shared.u64 t, %1; cvt.u32.u64 %0, t; }"
        : "=r"(a) : "l"(p));
    return a;
}
__device__ __forceinline__ uint32_t hpair(__half a, __half b) {
    __half2 t(a, b);                   // a = low 16 bits
    return *reinterpret_cast<uint32_t*>(&t);
}
__device__ __forceinline__ void mma_f16(float& d0, float& d1, float& d2, float& d3,
                                        uint32_t a0, uint32_t a1, uint32_t a2, uint32_t a3,
                                        uint32_t b0, uint32_t b1) {
    asm volatile(
        "mma.sync.aligned.m16n8k16.row.col.f32.f16.f16.f32 "
        "{%0,%1,%2,%3}, {%4,%5,%6,%7}, {%8,%9}, {%0,%1,%2,%3};"
        : "+f"(d0), "+f"(d1), "+f"(d2), "+f"(d3)
        : "r"(a0), "r"(a1), "r"(a2), "r"(a3), "r"(b0), "r"(b1));
}
__device__ __forceinline__ void ldsm_x2(uint32_t& r0, uint32_t& r1, uint32_t addr) {
    asm volatile("ldmatrix.sync.aligned.m8n8.x2.shared.b16 {%0,%1}, [%2];"
                 : "=r"(r0), "=r"(r1) : "r"(addr));
}
// merge two (best, best2, idx) candidate sets (union top-2), min-index tiebreak
__device__ __forceinline__ void merge_top2(float& b, float& b2, int& i, int off) {
    float ob  = __shfl_xor_sync(0xffffffffu, b,  off);
    float ob2 = __shfl_xor_sync(0xffffffffu, b2, off);
    int   oi  = __shfl_xor_sync(0xffffffffu, i,  off);
    int   ni  = (ob < b || (ob == b && oi < i)) ? oi : i;
    float nb2 = fminf(fmaxf(b, ob), fminf(b2, ob2));
    b  = fminf(b, ob);
    b2 = nb2;
    i  = ni;
}
// best/2nd scalar update (R12/R14-proven form)
#define UPD(tv, bb, bb2, ii, ca)                          \
    if ((tv) < (bb)) { (bb2) = (bb); (bb) = (tv); (ii) = (ca); } \
    else if ((tv) < (bb2)) (bb2) = (tv);

// ---------------------------------------------------------------------------
// Kernel 1: prep: e2 (fp32) + fp16 e*256 (|e|<=1/256 -> in [-1,1], rel err
// 2^-12). + reset flag counter.
// ---------------------------------------------------------------------------
__global__ void prep_kernel(const float* __restrict__ emb) {
    int j = blockIdx.x * blockDim.x + threadIdx.x;
    if (j == 0) g_flag_cnt = 0;
    if (j < NE) {
        const float* e = emb + (size_t)j * D;
        float s = 0.f;
        #pragma unroll
        for (int k = 0; k < D; k++) {
            float v = e[k];
            s += v * v;
            g_ef16[j * D + k] = __float2half_rn(v * 256.0f);
        }
        g_e2[j] = s;
    }
}

// ---------------------------------------------------------------------------
// Kernel 2: HMMA argmin, fp16 single-plane, TWO m16 row-tiles per warp x
// dual n-tile: each ldsm'd B fragment feeds 4 MMAs (ldsm count halved per
// unit work vs R15). cp.async double-buffered staging. R14-proven epilogue.
// ---------------------------------------------------------------------------
__global__ __launch_bounds__(256, 2)
void argmin_tc_kernel(const float* __restrict__ z,
                      float* __restrict__ idx_out_f) {
    __shared__ __align__(16) __half sB[2][NC * BSTRIDE];  // 2 x 9.2 KB
    __shared__ float sE2[2][NC];
    __shared__ float sLoss[8];

    int tid  = threadIdx.x;
    int wid  = tid >> 5;
    int lane = tid & 31;
    int grp  = lane >> 2;         // 0..7  (row within tile)
    int c    = lane & 3;          // 0..3  (pair column)

    uint32_t sb_base  = smem_u32(&sB[0][0]);
    uint32_t se2_base = smem_u32(&sE2[0][0]);

    // staging addresses for this thread (row = tid/4, quarter = tid%4, 32B)
    int srow = tid >> 2, sq = tid & 3;
    uint32_t dst_off = (uint32_t)srow * (BSTRIDE * 2) + (uint32_t)sq * 32;

    // ---- prefetch chunk 0 into buffer 0 ----
    {
        const char* src = (const char*)g_ef16 + (size_t)srow * (D * 2) + sq * 32;
        uint32_t dst = sb_base + dst_off;
        asm volatile("cp.async.ca.shared.global [%0], [%1], 16;" :: "r"(dst), "l"(src));
        asm volatile("cp.async.ca.shared.global [%0], [%1], 16;" :: "r"(dst + 16), "l"(src + 16));
        if (tid < NC) {
            const char* s2 = (const char*)g_e2 + (size_t)tid * 4;
            asm volatile("cp.async.ca.shared.global [%0], [%1], 4;"
                         :: "r"(se2_base + (uint32_t)tid * 4), "l"(s2));
        }
        asm volatile("cp.async.commit_group;" ::: "memory");
    }

    // ---- A fragments for BOTH row-tiles; z2 per row via quad shfl ----
    int rbase = blockIdx.x * M_TILE + wid * 16;
    int r0 = rbase + grp;               // tile0: rows r0, r0+8
    int r2 = rbase + 128 + grp;         // tile1: rows r2, r2+8
    uint32_t af0[16], af1[16];
    float z2_0 = 0.f, z2_1 = 0.f, z2_2 = 0.f, z2_3 = 0.f;
    {
        const float* za = z + (size_t)r0 * D;
        const float* zb = za + 8 * D;
        const float* zc = z + (size_t)r2 * D;
        const float* zd = zc + 8 * D;
        #pragma unroll
        for (int t = 0; t < 4; t++) {
            float2 p0 = *(const float2*)(za + 16 * t + 2 * c);
            float2 p1 = *(const float2*)(zb + 16 * t + 2 * c);
            float2 p2 = *(const float2*)(za + 16 * t + 8 + 2 * c);
            float2 p3 = *(const float2*)(zb + 16 * t + 8 + 2 * c);
            float2 q0 = *(const float2*)(zc + 16 * t + 2 * c);
            float2 q1 = *(const float2*)(zd + 16 * t + 2 * c);
            float2 q2 = *(const float2*)(zc + 16 * t + 8 + 2 * c);
            float2 q3 = *(const float2*)(zd + 16 * t + 8 + 2 * c);
            z2_0 += p0.x * p0.x + p0.y * p0.y + p2.x * p2.x + p2.y * p2.y;
            z2_1 += p1.x * p1.x + p1.y * p1.y + p3.x * p3.x + p3.y * p3.y;
            z2_2 += q0.x * q0.x + q0.y * q0.y + q2.x * q2.x + q2.y * q2.y;
            z2_3 += q1.x * q1.x + q1.y * q1.y + q3.x * q3.x + q3.y * q3.y;
            af0[t * 4 + 0] = hpair(__float2half_rn(p0.x), __float2half_rn(p0.y));
            af0[t * 4 + 1] = hpair(__float2half_rn(p1.x), __float2half_rn(p1.y));
            af0[t * 4 + 2] = hpair(__float2half_rn(p2.x), __float2half_rn(p2.y));
            af0[t * 4 + 3] = hpair(__float2half_rn(p3.x), __float2half_rn(p3.y));
            af1[t * 4 + 0] = hpair(__float2half_rn(q0.x), __float2half_rn(q0.y));
            af1[t * 4 + 1] = hpair(__float2half_rn(q1.x), __float2half_rn(q1.y));
            af1[t * 4 + 2] = hpair(__float2half_rn(q2.x), __float2half_rn(q2.y));
            af1[t * 4 + 3] = hpair(__float2half_rn(q3.x), __float2half_rn(q3.y));
        }
        #pragma unroll
        for (int o = 1; o <= 2; o <<= 1) {
            z2_0 += __shfl_xor_sync(0xffffffffu, z2_0, o);
            z2_1 += __shfl_xor_sync(0xffffffffu, z2_1, o);
            z2_2 += __shfl_xor_sync(0xffffffffu, z2_2, o);
            z2_3 += __shfl_xor_sync(0xffffffffu, z2_3, o);
        }
    }

    float b0 = 3.402823466e38f, b20 = 3.402823466e38f;  // row r0
    float b1 = 3.402823466e38f, b21 = 3.402823466e38f;  // row r0+8
    float b2 = 3.402823466e38f, b22 = 3.402823466e38f;  // row r2
    float b3 = 3.402823466e38f, b23 = 3.402823466e38f;  // row r2+8
    int   i0 = 0, i1 = 0, i2 = 0, i3 = 0;

    int ll = lane & 15;
    uint32_t lrow = (uint32_t)(ll & 7) * (BSTRIDE * 2) + ((uint32_t)(ll >> 3)) * 16;

    for (int ch = 0; ch < NUM_CHUNKS; ch++) {
        int buf = ch & 1;
        if (ch + 1 < NUM_CHUNKS) {
            int nb = (ch + 1) & 1;
            const char* src = (const char*)g_ef16
                + (size_t)((ch + 1) * NC + srow) * (D * 2) + sq * 32;
            uint32_t dst = sb_base + (uint32_t)nb * BUF_BYTES + dst_off;
            asm volatile("cp.async.ca.shared.global [%0], [%1], 16;" :: "r"(dst), "l"(src));
            asm volatile("cp.async.ca.shared.global [%0], [%1], 16;" :: "r"(dst + 16), "l"(src + 16));
            if (tid < NC) {
                const char* s2 = (const char*)g_e2 + (size_t)((ch + 1) * NC + tid) * 4;
                asm volatile("cp.async.ca.shared.global [%0], [%1], 4;"
                             :: "r"(se2_base + (uint32_t)nb * (NC * 4) + (uint32_t)tid * 4), "l"(s2));
            }
            asm volatile("cp.async.commit_group;" ::: "memory");
            asm volatile("cp.async.wait_group 1;" ::: "memory");
        } else {
            asm volatile("cp.async.wait_group 0;" ::: "memory");
        }
        __syncthreads();

        int cbase = ch * NC;
        uint32_t sbuf = sb_base + (uint32_t)buf * BUF_BYTES;
        const float* se2 = &sE2[buf][0];

        #pragma unroll 1
        for (int nt = 0; nt < NC / 8; nt += 2) {
            // row-tile0 accums (tiles nt, nt+1)
            float dA0 = 0.f, dA1 = 0.f, dA2 = 0.f, dA3 = 0.f;
            float dB0 = 0.f, dB1 = 0.f, dB2 = 0.f, dB3 = 0.f;
            // row-tile1 accums (tiles nt, nt+1)
            float dC0 = 0.f, dC1 = 0.f, dC2 = 0.f, dC3 = 0.f;
            float dD0 = 0.f, dD1 = 0.f, dD2 = 0.f, dD3 = 0.f;
            uint32_t baseA = (uint32_t)(nt * 8) * (BSTRIDE * 2) + lrow;
            uint32_t baseB = baseA + 8u * (BSTRIDE * 2);
            #pragma unroll
            for (int t = 0; t < 4; t++) {
                uint32_t ra0, ra1, rb0, rb1;
                ldsm_x2(ra0, ra1, sbuf + baseA + t * 32);
                ldsm_x2(rb0, rb1, sbuf + baseB + t * 32);
                mma_f16(dA0, dA1, dA2, dA3, af0[t*4+0], af0[t*4+1], af0[t*4+2], af0[t*4+3], ra0, ra1);
                mma_f16(dB0, dB1, dB2, dB3, af0[t*4+0], af0[t*4+1], af0[t*4+2], af0[t*4+3], rb0, rb1);
                mma_f16(dC0, dC1, dC2, dC3, af1[t*4+0], af1[t*4+1], af1[t*4+2], af1[t*4+3], ra0, ra1);
                mma_f16(dD0, dD1, dD2, dD3, af1[t*4+0], af1[t*4+1], af1[t*4+2], af1[t*4+3], rb0, rb1);
            }
            // ---- epilogue ----
            int caA = cbase + nt * 8 + 2 * c;
            int caB = caA + 8;
            float eaA = se2[nt * 8 + 2 * c];
            float ebA = se2[nt * 8 + 2 * c + 1];
            float eaB = se2[nt * 8 + 8 + 2 * c];
            float ebB = se2[nt * 8 + 8 + 2 * c + 1];
            float t00 = (z2_0 + eaA) - 2.f * (dA0 * INV256);
            float t01 = (z2_0 + ebA) - 2.f * (dA1 * INV256);
            float t02 = (z2_1 + eaA) - 2.f * (dA2 * INV256);
            float t03 = (z2_1 + ebA) - 2.f * (dA3 * INV256);
            float t10 = (z2_0 + eaB) - 2.f * (dB0 * INV256);
            float t11 = (z2_0 + ebB) - 2.f * (dB1 * INV256);
            float t12 = (z2_1 + eaB) - 2.f * (dB2 * INV256);
            float t13 = (z2_1 + ebB) - 2.f * (dB3 * INV256);
            float t20 = (z2_2 + eaA) - 2.f * (dC0 * INV256);
            float t21 = (z2_2 + ebA) - 2.f * (dC1 * INV256);
            float t22 = (z2_3 + eaA) - 2.f * (dC2 * INV256);
            float t23 = (z2_3 + ebA) - 2.f * (dC3 * INV256);
            float t30 = (z2_2 + eaB) - 2.f * (dD0 * INV256);
            float t31 = (z2_2 + ebB) - 2.f * (dD1 * INV256);
            float t32 = (z2_3 + eaB) - 2.f * (dD2 * INV256);
            float t33 = (z2_3 + ebB) - 2.f * (dD3 * INV256);
            UPD(t00, b0, b20, i0, caA);     UPD(t01, b0, b20, i0, caA + 1);
            UPD(t02, b1, b21, i1, caA);     UPD(t03, b1, b21, i1, caA + 1);
            UPD(t10, b0, b20, i0, caB);     UPD(t11, b0, b20, i0, caB + 1);
            UPD(t12, b1, b21, i1, caB);     UPD(t13, b1, b21, i1, caB + 1);
            UPD(t20, b2, b22, i2, caA);     UPD(t21, b2, b22, i2, caA + 1);
            UPD(t22, b3, b23, i3, caA);     UPD(t23, b3, b23, i3, caA + 1);
            UPD(t30, b2, b22, i2, caB);     UPD(t31, b2, b22, i2, caB + 1);
            UPD(t32, b3, b23, i3, caB);     UPD(t33, b3, b23, i3, caB + 1);
        }
        __syncthreads();   // protect this buffer before it is re-staged
    }

    // ---- merge across the 4 lanes of each row group ----
    merge_top2(b0, b20, i0, 1); merge_top2(b0, b20, i0, 2);
    merge_top2(b1, b21, i1, 1); merge_top2(b1, b21, i1, 2);
    merge_top2(b2, b22, i2, 1); merge_top2(b2, b22, i2, 2);
    merge_top2(b3, b23, i3, 1); merge_top2(b3, b23, i3, 2);

    if (c == 0) {
        int r1 = r0 + 8, r3 = r2 + 8;
        g_idx[r0] = i0;            g_idx[r1] = i1;
        g_idx[r2] = i2;            g_idx[r3] = i3;
        idx_out_f[r0] = (float)i0; idx_out_f[r1] = (float)i1;
        idx_out_f[r2] = (float)i2; idx_out_f[r3] = (float)i3;
        if (b20 - b0 < GAP_THRESH) { int s = atomicAdd(&g_flag_cnt, 1); g_flag_rows[s] = r0; }
        if (b21 - b1 < GAP_THRESH) { int s = atomicAdd(&g_flag_cnt, 1); g_flag_rows[s] = r1; }
        if (b22 - b2 < GAP_THRESH) { int s = atomicAdd(&g_flag_cnt, 1); g_flag_rows[s] = r2; }
        if (b23 - b3 < GAP_THRESH) { int s = atomicAdd(&g_flag_cnt, 1); g_flag_rows[s] = r3; }
    }

    // ---- loss partial: sum of bestd over the CTA's 256 rows ----
    float v = (c == 0) ? ((b0 + b1) + (b2 + b3)) : 0.f;
    #pragma unroll
    for (int o = 16; o > 0; o >>= 1) v += __shfl_down_sync(0xffffffffu, v, o);
    if (lane == 0) sLoss[wid] = v;
    __syncthreads();
    if (tid == 0) {
        float s = 0.f;
        #pragma unroll
        for (int w = 0; w < 8; w++) s += sLoss[w];
        g_partial[blockIdx.x] = s;
    }
}

// ---------------------------------------------------------------------------
// Kernel 2b: refine flagged rows (exact Kahan fp32 dots). 256 threads,
// 4 codes/thread. Rewrites g_idx + idx_out only.
// ---------------------------------------------------------------------------
__global__ __launch_bounds__(REFINE_THREADS)
void refine_kernel(const float* __restrict__ z,
                   const float* __restrict__ emb,
                   float* __restrict__ idx_out_f) {
    __shared__ float sz[D];
    __shared__ float sd[REFINE_THREADS];
    __shared__ int   si[REFINE_THREADS];

    int cnt = g_flag_cnt;
    for (int w = blockIdx.x; w < cnt; w += gridDim.x) {
        int row = g_flag_rows[w];

        __syncthreads();
        if (threadIdx.x < D) sz[threadIdx.x] = z[(size_t)row * D + threadIdx.x];
        __syncthreads();

        float z2 = 0.f;
        #pragma unroll
        for (int k = 0; k < D; k++) z2 += sz[k] * sz[k];

        float bestd = 3.402823466e38f;
        int   besti = NE;

        for (int j = threadIdx.x; j < NE; j += REFINE_THREADS) {
            const float4* e = (const float4*)(emb + (size_t)j * D);
            float4 ev[16];
            #pragma unroll
            for (int q = 0; q < 16; q++) ev[q] = e[q];

            float s = 0.f, cc = 0.f;
            #pragma unroll
            for (int q = 0; q < 16; q++) {
                float el[4] = {ev[q].x, ev[q].y, ev[q].z, ev[q].w};
                #pragma unroll
                for (int u = 0; u < 4; u++) {
                    float p = __fmul_rn(sz[q * 4 + u], el[u]);
                    float y = __fadd_rn(p, -cc);
                    float t = __fadd_rn(s, y);
                    cc = __fadd_rn(__fadd_rn(t, -s), -y);
                    s = t;
                }
            }
            float dot = __fadd_rn(s, cc);
            float dd  = __fadd_rn(__fadd_rn(z2, g_e2[j]), -2.f * dot);
            if (dd < bestd || (dd == bestd && j < besti)) { bestd = dd; besti = j; }
        }

        sd[threadIdx.x] = bestd;
        si[threadIdx.x] = besti;
        __syncthreads();
        #pragma unroll
        for (int st = REFINE_THREADS / 2; st > 0; st >>= 1) {
            if (threadIdx.x < st) {
                float od = sd[threadIdx.x + st];
                int   oi = si[threadIdx.x + st];
                if (od < sd[threadIdx.x] ||
                    (od == sd[threadIdx.x] && oi < si[threadIdx.x])) {
                    sd[threadIdx.x] = od;
                    si[threadIdx.x] = oi;
                }
            }
            __syncthreads();
        }
        if (threadIdx.x == 0) {
            g_idx[row]     = si[0];
            idx_out_f[row] = (float)si[0];
        }
        __syncthreads();
    }
}

// ---------------------------------------------------------------------------
// Kernel 3: zq gather, 8 threads/row (2 float4 each) for latency hiding.
// out = z + (e - z) (straight-through). zq_out 4B-aligned -> scalar stores.
// ---------------------------------------------------------------------------
__global__ __launch_bounds__(K3_THREADS)
void gather_kernel(const float* __restrict__ z,
                   const float* __restrict__ emb,
                   float* __restrict__ zq_out) {
    int gt   = blockIdx.x * K3_THREADS + threadIdx.x;
    int row  = gt >> 3;
    int part = gt & 7;
    int j    = g_idx[row];

    const float4* ef = (const float4*)(emb + (size_t)j * D + part * 8);
    const float4* zf = (const float4*)(z + (size_t)row * D + part * 8);
    float*        o  = zq_out + (size_t)row * D + part * 8;

    #pragma unroll
    for (int q = 0; q < 2; q++) {
        float4 e  = ef[q];
        float4 zv = zf[q];
        o[q * 4 + 0] = __fadd_rn(zv.x, __fadd_rn(e.x, -zv.x));
        o[q * 4 + 1] = __fadd_rn(zv.y, __fadd_rn(e.y, -zv.y));
        o[q * 4 + 2] = __fadd_rn(zv.z, __fadd_rn(e.z, -zv.z));
        o[q * 4 + 3] = __fadd_rn(zv.w, __fadd_rn(e.w, -zv.w));
    }
}

// ---------------------------------------------------------------------------
// Kernel 4: final loss reduction over 256 partials.
// loss = 1.25 * sum / (N*D)
// ---------------------------------------------------------------------------
__global__ void final_kernel(float* __restrict__ out) {
    __shared__ float red[GRID_MAIN];
    red[threadIdx.x] = g_partial[threadIdx.x];
    __syncthreads();
    #pragma unroll
    for (int st = GRID_MAIN / 2; st > 0; st >>= 1) {
        if (threadIdx.x < st) red[threadIdx.x] += red[threadIdx.x + st];
        __syncthreads();
    }
    if (threadIdx.x == 0)
        out[0] = 1.25f * red[0] / (float)(N_ROWS * D);
}

// ---------------------------------------------------------------------------
// Launch: out layout = [loss(1) | z_q(N_ROWS*D) | indices(N_ROWS)] fp32
// ---------------------------------------------------------------------------
extern "C" void kernel_launch(void* const* d_in, const int* in_sizes, int n_in,
                              void* d_out, int out_size) {
    const float* z   = (const float*)d_in[0];
    const float* emb = (const float*)d_in[1];
    float* out     = (float*)d_out;
    float* zq_out  = out + 1;
    float* idx_out = out + 1 + (size_t)N_ROWS * D;

    prep_kernel<<<4, 256>>>(emb);
    argmin_tc_kernel<<<GRID_MAIN, 256>>>(z, idx_out);
    refine_kernel<<<REFINE_BLOCKS, REFINE_THREADS>>>(z, emb, idx_out);
    gather_kernel<<<K3_BLOCKS, K3_THREADS>>>(z, emb, zq_out);
    final_kernel<<<1, GRID_MAIN>>>(out);
}

// round 17
// speedup vs baseline: 1.0668x; 1.0668x over previous
#include <cuda_runtime.h>
#include <cuda_fp16.h>
#include <cstdint>

#define N_ROWS 65536
#define D      64
#define NE     1024
#define M_TILE 128                     // rows per CTA (8 warps x m16)
#define NC     64                      // codes per chunk
#define NUM_CHUNKS (NE / NC)           // 16
#define GRID_MAIN (N_ROWS / M_TILE)    // 512
#define GAP_THRESH 1.5e-4f
#define REFINE_BLOCKS 256
#define REFINE_THREADS 256
#define K3_THREADS 256
#define K3_BLOCKS  (N_ROWS * 8 / K3_THREADS)   // 8 threads/row -> 2048
#define BSTRIDE 72                     // padded smem row stride (elems) = 144 B
#define BUF_BYTES (NC * BSTRIDE * 2)   // 9216 B per buffer
#define NEG2_256 (-0.0078125f)         // -2/256

// ---------------- scratch (no allocations allowed) ----------------
__device__ float g_e2[NE];
__device__ __align__(16) __half g_ef16[NE * D];   // e * 256 in fp16
__device__ int   g_idx[N_ROWS];
__device__ float g_partial[GRID_MAIN];
__device__ int   g_flag_cnt;
__device__ int   g_flag_rows[N_ROWS];

// ---------------- helpers ----------------
__device__ __forceinline__ uint32_t smem_u32(const void* p) {
    uint32_t a;
    asm("{ .reg .u64 t; cvta.to.shared.u64 t, %1; cvt.u32.u64 %0, t; }"
        : "=r"(a) : "l"(p));
    return a;
}
__device__ __forceinline__ uint32_t hpair(__half a, __half b) {
    __half2 t(a, b);                   // a = low 16 bits
    return *reinterpret_cast<uint32_t*>(&t);
}
__device__ __forceinline__ void mma_f16(float& d0, float& d1, float& d2, float& d3,
                                        uint32_t a0, uint32_t a1, uint32_t a2, uint32_t a3,
                                        uint32_t b0, uint32_t b1) {
    asm volatile(
        "mma.sync.aligned.m16n8k16.row.col.f32.f16.f16.f32 "
        "{%0,%1,%2,%3}, {%4,%5,%6,%7}, {%8,%9}, {%0,%1,%2,%3};"
        : "+f"(d0), "+f"(d1), "+f"(d2), "+f"(d3)
        : "r"(a0), "r"(a1), "r"(a2), "r"(a3), "r"(b0), "r"(b1));
}
__device__ __forceinline__ void ldsm_x2(uint32_t& r0, uint32_t& r1, uint32_t addr) {
    asm volatile("ldmatrix.sync.aligned.m8n8.x2.shared.b16 {%0,%1}, [%2];"
                 : "=r"(r0), "=r"(r1) : "r"(addr));
}
// merge two (best, best2, idx) candidate sets (union top-2), min-index tiebreak
__device__ __forceinline__ void merge_top2(float& b, float& b2, int& i, int off) {
    float ob  = __shfl_xor_sync(0xffffffffu, b,  off);
    float ob2 = __shfl_xor_sync(0xffffffffu, b2, off);
    int   oi  = __shfl_xor_sync(0xffffffffu, i,  off);
    int   ni  = (ob < b || (ob == b && oi < i)) ? oi : i;
    float nb2 = fminf(fmaxf(b, ob), fminf(b2, ob2));
    b  = fminf(b, ob);
    b2 = nb2;
    i  = ni;
}

// ---------------------------------------------------------------------------
// Kernel 1: prep: e2 (fp32) + fp16 e*256 (|e|<=1/256 -> in [-1,1], rel err
// 2^-12). + reset flag counter.
// ---------------------------------------------------------------------------
__global__ void prep_kernel(const float* __restrict__ emb) {
    int j = blockIdx.x * blockDim.x + threadIdx.x;
    if (j == 0) g_flag_cnt = 0;
    if (j < NE) {
        const float* e = emb + (size_t)j * D;
        float s = 0.f;
        #pragma unroll
        for (int k = 0; k < D; k++) {
            float v = e[k];
            s += v * v;
            g_ef16[j * D + k] = __float2half_rn(v * 256.0f);
        }
        g_e2[j] = s;
    }
}

// ---------------------------------------------------------------------------
// Kernel 2: HMMA argmin (R15 config: fp16 single-plane, dual n-tile ILP,
// cp.async double-buffered staging, occ 3) + FOLDED-z2 epilogue:
// track t = e2 - 2*dot (z2 row-constant -> identical argmin/gap/tiebreak),
// ONE FFMA per candidate: t = fma(d, -2/256, e2). Loss = sum(z2 + t1),
// the R13-validated (rel_err 0.0) loss path.
// ---------------------------------------------------------------------------
__global__ __launch_bounds__(256, 3)
void argmin_tc_kernel(const float* __restrict__ z,
                      float* __restrict__ idx_out_f) {
    __shared__ __align__(16) __half sB[2][NC * BSTRIDE];  // 2 x 9.2 KB
    __shared__ float sE2[2][NC];
    __shared__ float sLoss[8];

    int tid  = threadIdx.x;
    int wid  = tid >> 5;
    int lane = tid & 31;
    int grp  = lane >> 2;         // 0..7  (row within tile)
    int c    = lane & 3;          // 0..3  (pair column)

    uint32_t sb_base  = smem_u32(&sB[0][0]);
    uint32_t se2_base = smem_u32(&sE2[0][0]);

    // staging addresses for this thread (row = tid/4, quarter = tid%4, 32B)
    int srow = tid >> 2, sq = tid & 3;
    uint32_t dst_off = (uint32_t)srow * (BSTRIDE * 2) + (uint32_t)sq * 32;

    // ---- prefetch chunk 0 into buffer 0 ----
    {
        const char* src = (const char*)g_ef16 + (size_t)srow * (D * 2) + sq * 32;
        uint32_t dst = sb_base + dst_off;
        asm volatile("cp.async.ca.shared.global [%0], [%1], 16;" :: "r"(dst), "l"(src));
        asm volatile("cp.async.ca.shared.global [%0], [%1], 16;" :: "r"(dst + 16), "l"(src + 16));
        if (tid < NC) {
            const char* s2 = (const char*)g_e2 + (size_t)tid * 4;
            asm volatile("cp.async.ca.shared.global [%0], [%1], 4;"
                         :: "r"(se2_base + (uint32_t)tid * 4), "l"(s2));
        }
        asm volatile("cp.async.commit_group;" ::: "memory");
    }

    // ---- A fragments (single-plane fp16) from gmem; z2 via group shfl ----
    int rbase = blockIdx.x * M_TILE + wid * 16;
    int r0 = rbase + grp;         // rows grp and grp+8 of this warp's m16 tile
    uint32_t af[16];
    float z2_0 = 0.f, z2_1 = 0.f;
    {
        const float* zr0 = z + (size_t)r0 * D;
        const float* zr1 = zr0 + 8 * D;
        #pragma unroll
        for (int t = 0; t < 4; t++) {
            float2 p0 = *(const float2*)(zr0 + 16 * t + 2 * c);
            float2 p1 = *(const float2*)(zr1 + 16 * t + 2 * c);
            float2 p2 = *(const float2*)(zr0 + 16 * t + 8 + 2 * c);
            float2 p3 = *(const float2*)(zr1 + 16 * t + 8 + 2 * c);
            z2_0 += p0.x * p0.x + p0.y * p0.y + p2.x * p2.x + p2.y * p2.y;
            z2_1 += p1.x * p1.x + p1.y * p1.y + p3.x * p3.x + p3.y * p3.y;
            af[t * 4 + 0] = hpair(__float2half_rn(p0.x), __float2half_rn(p0.y));
            af[t * 4 + 1] = hpair(__float2half_rn(p1.x), __float2half_rn(p1.y));
            af[t * 4 + 2] = hpair(__float2half_rn(p2.x), __float2half_rn(p2.y));
            af[t * 4 + 3] = hpair(__float2half_rn(p3.x), __float2half_rn(p3.y));
        }
        z2_0 += __shfl_xor_sync(0xffffffffu, z2_0, 1);
        z2_0 += __shfl_xor_sync(0xffffffffu, z2_0, 2);
        z2_1 += __shfl_xor_sync(0xffffffffu, z2_1, 1);
        z2_1 += __shfl_xor_sync(0xffffffffu, z2_1, 2);
    }

    float b0 = 3.402823466e38f, b20 = 3.402823466e38f;  // row r0 (t-domain)
    float b1 = 3.402823466e38f, b21 = 3.402823466e38f;  // row r0+8
    int   i0 = 0, i1 = 0;

    int ll = lane & 15;
    uint32_t lrow = (uint32_t)(ll & 7) * (BSTRIDE * 2) + ((uint32_t)(ll >> 3)) * 16;

    for (int ch = 0; ch < NUM_CHUNKS; ch++) {
        int buf = ch & 1;
        // ---- prefetch next chunk into the other buffer, then wait for this one
        if (ch + 1 < NUM_CHUNKS) {
            int nb = (ch + 1) & 1;
            const char* src = (const char*)g_ef16
                + (size_t)((ch + 1) * NC + srow) * (D * 2) + sq * 32;
            uint32_t dst = sb_base + (uint32_t)nb * BUF_BYTES + dst_off;
            asm volatile("cp.async.ca.shared.global [%0], [%1], 16;" :: "r"(dst), "l"(src));
            asm volatile("cp.async.ca.shared.global [%0], [%1], 16;" :: "r"(dst + 16), "l"(src + 16));
            if (tid < NC) {
                const char* s2 = (const char*)g_e2 + (size_t)((ch + 1) * NC + tid) * 4;
                asm volatile("cp.async.ca.shared.global [%0], [%1], 4;"
                             :: "r"(se2_base + (uint32_t)nb * (NC * 4) + (uint32_t)tid * 4), "l"(s2));
            }
            asm volatile("cp.async.commit_group;" ::: "memory");
            asm volatile("cp.async.wait_group 1;" ::: "memory");
        } else {
            asm volatile("cp.async.wait_group 0;" ::: "memory");
        }
        __syncthreads();

        int cbase = ch * NC;
        uint32_t sbuf = sb_base + (uint32_t)buf * BUF_BYTES;
        const float* se2 = &sE2[buf][0];

        #pragma unroll 1
        for (int nt = 0; nt < NC / 8; nt += 2) {
            float dA0 = 0.f, dA1 = 0.f, dA2 = 0.f, dA3 = 0.f;  // tile nt
            float dB0 = 0.f, dB1 = 0.f, dB2 = 0.f, dB3 = 0.f;  // tile nt+1
            uint32_t baseA = (uint32_t)(nt * 8) * (BSTRIDE * 2) + lrow;
            uint32_t baseB = baseA + 8u * (BSTRIDE * 2);
            #pragma unroll
            for (int t = 0; t < 4; t++) {
                uint32_t ra0, ra1, rb0, rb1;
                ldsm_x2(ra0, ra1, sbuf + baseA + t * 32);
                ldsm_x2(rb0, rb1, sbuf + baseB + t * 32);
                mma_f16(dA0, dA1, dA2, dA3, af[t*4+0], af[t*4+1], af[t*4+2], af[t*4+3], ra0, ra1);
                mma_f16(dB0, dB1, dB2, dB3, af[t*4+0], af[t*4+1], af[t*4+2], af[t*4+3], rb0, rb1);
            }
            // ---- folded epilogue: t = fma(d, -2/256, e2); top-2 track ----
            int caA = cbase + nt * 8 + 2 * c;
            int caB = caA + 8;
            float eaA = se2[nt * 8 + 2 * c];
            float ebA = se2[nt * 8 + 2 * c + 1];
            float eaB = se2[nt * 8 + 8 + 2 * c];
            float ebB = se2[nt * 8 + 8 + 2 * c + 1];
            float t00 = fmaf(dA0, NEG2_256, eaA);
            float t01 = fmaf(dA1, NEG2_256, ebA);
            float t02 = fmaf(dA2, NEG2_256, eaA);
            float t03 = fmaf(dA3, NEG2_256, ebA);
            float t10 = fmaf(dB0, NEG2_256, eaB);
            float t11 = fmaf(dB1, NEG2_256, ebB);
            float t12 = fmaf(dB2, NEG2_256, eaB);
            float t13 = fmaf(dB3, NEG2_256, ebB);
            if (t00 < b0) { b20 = b0; b0 = t00; i0 = caA; }
            else if (t00 < b20) b20 = t00;
            if (t01 < b0) { b20 = b0; b0 = t01; i0 = caA + 1; }
            else if (t01 < b20) b20 = t01;
            if (t02 < b1) { b21 = b1; b1 = t02; i1 = caA; }
            else if (t02 < b21) b21 = t02;
            if (t03 < b1) { b21 = b1; b1 = t03; i1 = caA + 1; }
            else if (t03 < b21) b21 = t03;
            if (t10 < b0) { b20 = b0; b0 = t10; i0 = caB; }
            else if (t10 < b20) b20 = t10;
            if (t11 < b0) { b20 = b0; b0 = t11; i0 = caB + 1; }
            else if (t11 < b20) b20 = t11;
            if (t12 < b1) { b21 = b1; b1 = t12; i1 = caB; }
            else if (t12 < b21) b21 = t12;
            if (t13 < b1) { b21 = b1; b1 = t13; i1 = caB + 1; }
            else if (t13 < b21) b21 = t13;
        }
        __syncthreads();   // protect this buffer before it is re-staged
    }

    // ---- merge across the 4 lanes of each row group ----
    merge_top2(b0, b20, i0, 1); merge_top2(b0, b20, i0, 2);
    merge_top2(b1, b21, i1, 1); merge_top2(b1, b21, i1, 2);

    if (c == 0) {
        int r1 = r0 + 8;
        g_idx[r0] = i0;            g_idx[r1] = i1;
        idx_out_f[r0] = (float)i0; idx_out_f[r1] = (float)i1;
        if (b20 - b0 < GAP_THRESH) { int s = atomicAdd(&g_flag_cnt, 1); g_flag_rows[s] = r0; }
        if (b21 - b1 < GAP_THRESH) { int s = atomicAdd(&g_flag_cnt, 1); g_flag_rows[s] = r1; }
    }

    // ---- loss partial: bestd = z2 + t1 per row (R13-validated path) ----
    float v = (c == 0) ? ((z2_0 + b0) + (z2_1 + b1)) : 0.f;
    #pragma unroll
    for (int o = 16; o > 0; o >>= 1) v += __shfl_down_sync(0xffffffffu, v, o);
    if (lane == 0) sLoss[wid] = v;
    __syncthreads();
    if (tid == 0) {
        float s = 0.f;
        #pragma unroll
        for (int w = 0; w < 8; w++) s += sLoss[w];
        g_partial[blockIdx.x] = s;
    }
}

// ---------------------------------------------------------------------------
// Kernel 2b: refine flagged rows (exact Kahan fp32 dots). 256 threads,
// 4 codes/thread. Rewrites g_idx + idx_out only.
// ---------------------------------------------------------------------------
__global__ __launch_bounds__(REFINE_THREADS)
void refine_kernel(const float* __restrict__ z,
                   const float* __restrict__ emb,
                   float* __restrict__ idx_out_f) {
    __shared__ float sz[D];
    __shared__ float sd[REFINE_THREADS];
    __shared__ int   si[REFINE_THREADS];

    int cnt = g_flag_cnt;
    for (int w = blockIdx.x; w < cnt; w += gridDim.x) {
        int row = g_flag_rows[w];

        __syncthreads();
        if (threadIdx.x < D) sz[threadIdx.x] = z[(size_t)row * D + threadIdx.x];
        __syncthreads();

        float z2 = 0.f;
        #pragma unroll
        for (int k = 0; k < D; k++) z2 += sz[k] * sz[k];

        float bestd = 3.402823466e38f;
        int   besti = NE;

        for (int j = threadIdx.x; j < NE; j += REFINE_THREADS) {
            const float4* e = (const float4*)(emb + (size_t)j * D);
            float4 ev[16];
            #pragma unroll
            for (int q = 0; q < 16; q++) ev[q] = e[q];

            float s = 0.f, cc = 0.f;
            #pragma unroll
            for (int q = 0; q < 16; q++) {
                float el[4] = {ev[q].x, ev[q].y, ev[q].z, ev[q].w};
                #pragma unroll
                for (int u = 0; u < 4; u++) {
                    float p = __fmul_rn(sz[q * 4 + u], el[u]);
                    float y = __fadd_rn(p, -cc);
                    float t = __fadd_rn(s, y);
                    cc = __fadd_rn(__fadd_rn(t, -s), -y);
                    s = t;
                }
            }
            float dot = __fadd_rn(s, cc);
            float dd  = __fadd_rn(__fadd_rn(z2, g_e2[j]), -2.f * dot);
            if (dd < bestd || (dd == bestd && j < besti)) { bestd = dd; besti = j; }
        }

        sd[threadIdx.x] = bestd;
        si[threadIdx.x] = besti;
        __syncthreads();
        #pragma unroll
        for (int st = REFINE_THREADS / 2; st > 0; st >>= 1) {
            if (threadIdx.x < st) {
                float od = sd[threadIdx.x + st];
                int   oi = si[threadIdx.x + st];
                if (od < sd[threadIdx.x] ||
                    (od == sd[threadIdx.x] && oi < si[threadIdx.x])) {
                    sd[threadIdx.x] = od;
                    si[threadIdx.x] = oi;
                }
            }
            __syncthreads();
        }
        if (threadIdx.x == 0) {
            g_idx[row]     = si[0];
            idx_out_f[row] = (float)si[0];
        }
        __syncthreads();
    }
}

// ---------------------------------------------------------------------------
// Kernel 3: zq gather, 8 threads/row (2 float4 each) for latency hiding.
// out = z + (e - z) (straight-through). zq_out 4B-aligned -> scalar stores.
// ---------------------------------------------------------------------------
__global__ __launch_bounds__(K3_THREADS)
void gather_kernel(const float* __restrict__ z,
                   const float* __restrict__ emb,
                   float* __restrict__ zq_out) {
    int gt   = blockIdx.x * K3_THREADS + threadIdx.x;
    int row  = gt >> 3;
    int part = gt & 7;
    int j    = g_idx[row];

    const float4* ef = (const float4*)(emb + (size_t)j * D + part * 8);
    const float4* zf = (const float4*)(z + (size_t)row * D + part * 8);
    float*        o  = zq_out + (size_t)row * D + part * 8;

    #pragma unroll
    for (int q = 0; q < 2; q++) {
        float4 e  = ef[q];
        float4 zv = zf[q];
        o[q * 4 + 0] = __fadd_rn(zv.x, __fadd_rn(e.x, -zv.x));
        o[q * 4 + 1] = __fadd_rn(zv.y, __fadd_rn(e.y, -zv.y));
        o[q * 4 + 2] = __fadd_rn(zv.z, __fadd_rn(e.z, -zv.z));
        o[q * 4 + 3] = __fadd_rn(zv.w, __fadd_rn(e.w, -zv.w));
    }
}

// ---------------------------------------------------------------------------
// Kernel 4: final loss reduction over 512 partials.
// loss = 1.25 * sum / (N*D)
// ---------------------------------------------------------------------------
__global__ void final_kernel(float* __restrict__ out) {
    __shared__ float red[256];
    red[threadIdx.x] = g_partial[threadIdx.x] + g_partial[threadIdx.x + 256];
    __syncthreads();
    #pragma unroll
    for (int st = 128; st > 0; st >>= 1) {
        if (threadIdx.x < st) red[threadIdx.x] += red[threadIdx.x + st];
        __syncthreads();
    }
    if (threadIdx.x == 0)
        out[0] = 1.25f * red[0] / (float)(N_ROWS * D);
}

// ---------------------------------------------------------------------------
// Launch: out layout = [loss(1) | z_q(N_ROWS*D) | indices(N_ROWS)] fp32
// ---------------------------------------------------------------------------
extern "C" void kernel_launch(void* const* d_in, const int* in_sizes, int n_in,
                              void* d_out, int out_size) {
    const float* z   = (const float*)d_in[0];
    const float* emb = (const float*)d_in[1];
    float* out     = (float*)d_out;
    float* zq_out  = out + 1;
    float* idx_out = out + 1 + (size_t)N_ROWS * D;

    prep_kernel<<<4, 256>>>(emb);
    argmin_tc_kernel<<<GRID_MAIN, 256>>>(z, idx_out);
    refine_kernel<<<REFINE_BLOCKS, REFINE_THREADS>>>(z, emb, idx_out);
    gather_kernel<<<K3_BLOCKS, K3_THREADS>>>(z, emb, zq_out);
    final_kernel<<<1, 256>>>(out);
}